// round 8
// baseline (speedup 1.0000x reference)
#include <cuda_runtime.h>
#include <cstdint>

typedef unsigned int u32;
typedef unsigned long long u64;

#define NPG   64
#define IN_F  128
#define OUT_F 128
#define XS_STRIDE 132   // A-LDS.32 banks: gid*4 + tig -> conflict-free
#define WP_STRIDE 264   // (256+8); 264 % 32 == 8 -> B-LDS.64 banks tig*8+gid*2, conflict-free/phase

#define CVT_TF32(d, s) asm("cvt.rna.tf32.f32 %0, %1;" : "=r"(d) : "f"(s))

__device__ __forceinline__ void mma_tf32(float* c,
                                         u32 a0, u32 a1, u32 a2, u32 a3,
                                         u32 b0, u32 b1)
{
    asm volatile(
        "mma.sync.aligned.m16n8k8.row.col.f32.tf32.tf32.f32 "
        "{%0,%1,%2,%3}, {%4,%5,%6,%7}, {%8,%9}, {%0,%1,%2,%3};"
        : "+f"(c[0]), "+f"(c[1]), "+f"(c[2]), "+f"(c[3])
        : "r"(a0), "r"(a1), "r"(a2), "r"(a3), "r"(b0), "r"(b1));
}

#define WP_WORDS (64 * WP_STRIDE)            // 16896 (64 k-pair rows x 256 interleaved words + pad)
#define XS_WORDS (NPG * XS_STRIDE)           // 8448
#define SMEM_BYTES ((WP_WORDS + XS_WORDS) * 4)   // 101376

__global__ void __launch_bounds__(512, 2)
mhl_mma_kernel(const float* __restrict__ x,
               const int*   __restrict__ head,
               const float* __restrict__ kern,
               const float* __restrict__ bias,
               float*       __restrict__ out)
{
    extern __shared__ u32 smem[];
    u32* Wp = smem;              // tf32 W pairs: row r=(s*4+tig) holds {W[8s+tig][n], W[8s+tig+4][n]} interleaved
    u32* Xs = smem + WP_WORDS;   // tf32 X[node][k], stride 132

    const int tid  = threadIdx.x;
    const int wid  = tid >> 5;            // 16 warps: 4m x 4n
    const int lane = tid & 31;
    const int gid  = lane >> 2;
    const int tig  = lane & 3;
    const int g    = blockIdx.x;
    const int h    = __ldg(head + g);

    const int m0 = (wid >> 2) * 16;       // 0,16,32,48
    const int n0 = (wid & 3) * 32;        // 0,32,64,96

    // ---- stage W[h] -> smem tf32, k-pair interleaved ----
    {
        const float4* W4 = (const float4*)(kern + (size_t)h * IN_F * OUT_F);
        #pragma unroll
        for (int it = 0; it < 4; it++) {
            const int idx = tid + it * 512;       // 2048 pair-chunks
            const int r   = idx >> 5;             // pair-row 0..63
            const int c4  = idx & 31;             // float4 col
            const int s   = r >> 2;
            const int tg  = r & 3;
            const int k   = s * 8 + tg;
            float4 va = W4[k * 32 + c4];
            float4 vb = W4[(k + 4) * 32 + c4];
            u32 a0,a1,a2,a3,b0,b1,b2,b3;
            CVT_TF32(a0, va.x); CVT_TF32(a1, va.y); CVT_TF32(a2, va.z); CVT_TF32(a3, va.w);
            CVT_TF32(b0, vb.x); CVT_TF32(b1, vb.y); CVT_TF32(b2, vb.z); CVT_TF32(b3, vb.w);
            u32* dst = &Wp[r * WP_STRIDE + c4 * 8];
            dst[0] = a0; dst[1] = b0; dst[2] = a1; dst[3] = b1;
            dst[4] = a2; dst[5] = b2; dst[6] = a3; dst[7] = b3;
        }
    }
    // ---- stage X[g] -> smem tf32 ----
    {
        const float4* X4 = (const float4*)(x + (size_t)g * NPG * IN_F);
        #pragma unroll
        for (int it = 0; it < 4; it++) {
            const int idx  = tid + it * 512;      // 2048 float4
            const int node = idx >> 5;
            const int c4   = idx & 31;
            float4 v = X4[idx];
            u32 r0, r1, r2, r3;
            CVT_TF32(r0, v.x); CVT_TF32(r1, v.y);
            CVT_TF32(r2, v.z); CVT_TF32(r3, v.w);
            u32* dst = &Xs[node * XS_STRIDE + c4 * 4];
            dst[0] = r0; dst[1] = r1; dst[2] = r2; dst[3] = r3;
        }
    }
    __syncthreads();

    float acc[4][4];
    #pragma unroll
    for (int j = 0; j < 4; j++)
        #pragma unroll
        for (int r = 0; r < 4; r++)
            acc[j][r] = 0.0f;

    const u32* pX = Xs + (m0 + gid) * XS_STRIDE + tig;       // A base (row gid, +8)
    const u32* pB = Wp + tig * WP_STRIDE + (n0 + gid) * 2;   // B base (pair row tig)

    #pragma unroll
    for (int s = 0; s < 16; s++) {
        // A fragments: one m-tile, conflict-free LDS.32
        const u32* pa = pX + s * 8;
        u32 a0 = pa[0];
        u32 a1 = pa[8 * XS_STRIDE];
        u32 a2 = pa[4];
        u32 a3 = pa[8 * XS_STRIDE + 4];
        // B fragments: 4 n-tiles, one LDS.64 each ({k, k+4} interleaved pair)
        const u32* pb = pB + s * 4 * WP_STRIDE;
        #pragma unroll
        for (int j = 0; j < 4; j++) {
            u64 w = *(const u64*)(pb + j * 16);
            u32 b0 = (u32)w, b1 = (u32)(w >> 32);
            mma_tf32(acc[j], a0, a1, a2, a3, b0, b1);
        }
    }

    // ---- epilogue: bias + coalesced float2 stores ----
    float bb[4][2];
    #pragma unroll
    for (int j = 0; j < 4; j++) {
        const int col = n0 + 8 * j + 2 * tig;
        bb[j][0] = __ldg(bias + (size_t)h * OUT_F + col);
        bb[j][1] = __ldg(bias + (size_t)h * OUT_F + col + 1);
    }

    const int node0 = g * NPG + m0 + gid;
    #pragma unroll
    for (int j = 0; j < 4; j++) {
        const int col = n0 + 8 * j + 2 * tig;
        float2 v0 = make_float2(acc[j][0] + bb[j][0], acc[j][1] + bb[j][1]);
        float2 v1 = make_float2(acc[j][2] + bb[j][0], acc[j][3] + bb[j][1]);
        *(float2*)&out[(size_t)node0 * OUT_F + col]       = v0;
        *(float2*)&out[(size_t)(node0 + 8) * OUT_F + col] = v1;
    }
}

extern "C" void kernel_launch(void* const* d_in, const int* in_sizes, int n_in,
                              void* d_out, int out_size)
{
    const float* inputs = (const float*)d_in[0];
    const int*   head   = (const int*)d_in[2];
    const float* kern   = (const float*)d_in[3];
    const float* bias   = (const float*)d_in[4];
    float*       out    = (float*)d_out;
    const int n_graphs  = in_sizes[2];   // 256

    static bool attr_set = false;
    if (!attr_set) {
        cudaFuncSetAttribute(mhl_mma_kernel, cudaFuncAttributeMaxDynamicSharedMemorySize, SMEM_BYTES);
        attr_set = true;
    }
    mhl_mma_kernel<<<n_graphs, 512, SMEM_BYTES>>>(inputs, head, kern, bias, out);
}

// round 9
// speedup vs baseline: 1.1910x; 1.1910x over previous
#include <cuda_runtime.h>
#include <cuda_fp16.h>
#include <cstdint>

typedef unsigned int u32;

#define NPG   64
#define IN_F  128
#define OUT_F 128
#define XS2   68    // X row stride in half2 words: A banks gid*4+tig -> conflict-free
#define WS2   136   // W pair-row stride in half2 words: B banks tig*8+gid -> conflict-free

__device__ __forceinline__ u32 pack_h2(float lo, float hi) {
    __half2 h = __floats2half2_rn(lo, hi);
    return *(u32*)&h;
}

__device__ __forceinline__ void mma_f16(float* c, u32 a0, u32 a1, u32 a2, u32 a3,
                                        u32 b0, u32 b1)
{
    asm volatile(
        "mma.sync.aligned.m16n8k16.row.col.f32.f16.f16.f32 "
        "{%0,%1,%2,%3}, {%4,%5,%6,%7}, {%8,%9}, {%0,%1,%2,%3};"
        : "+f"(c[0]), "+f"(c[1]), "+f"(c[2]), "+f"(c[3])
        : "r"(a0), "r"(a1), "r"(a2), "r"(a3), "r"(b0), "r"(b1));
}

#define WP_WORDS (64 * WS2)                      // u32 words (half2 units)
#define XP_WORDS (NPG * XS2)
#define SMEM_BYTES ((WP_WORDS + XP_WORDS) * 4)   // 52224 B

__global__ void __launch_bounds__(512, 2)
mhl_mma_kernel(const float* __restrict__ x,
               const int*   __restrict__ head,
               const float* __restrict__ kern,
               const float* __restrict__ bias,
               float*       __restrict__ out)
{
    extern __shared__ u32 smem[];
    u32* Wp = smem;               // half2 W pairs: row r -> (W[2r][n], W[2r+1][n])
    u32* Xp = smem + WP_WORDS;    // half2 X pairs: Xp[node][k/2] = (X[node][2kp], X[node][2kp+1])

    const int tid  = threadIdx.x;
    const int wid  = tid >> 5;            // 16 warps: 4m x 4n
    const int lane = tid & 31;
    const int gid  = lane >> 2;
    const int tig  = lane & 3;
    const int g    = blockIdx.x;
    const int h    = __ldg(head + g);

    const int m0 = (wid >> 2) * 16;       // 0,16,32,48
    const int n0 = (wid & 3) * 32;        // 0,32,64,96

    // ---- stage W[h] -> smem fp16, k-pair packed (STS.128) ----
    {
        const float4* W4 = (const float4*)(kern + (size_t)h * IN_F * OUT_F);
        #pragma unroll
        for (int it = 0; it < 4; it++) {
            const int idx = tid + it * 512;       // 2048 pair-chunks
            const int r   = idx >> 5;             // k-pair row 0..63
            const int c4  = idx & 31;             // float4 col group
            float4 va = W4[(2 * r)     * 32 + c4];
            float4 vb = W4[(2 * r + 1) * 32 + c4];
            uint4 o;
            o.x = pack_h2(va.x, vb.x);
            o.y = pack_h2(va.y, vb.y);
            o.z = pack_h2(va.z, vb.z);
            o.w = pack_h2(va.w, vb.w);
            *(uint4*)&Wp[r * WS2 + c4 * 4] = o;
        }
    }
    // ---- stage X[g] -> smem fp16 pairs (STS.64) ----
    {
        const float4* X4 = (const float4*)(x + (size_t)g * NPG * IN_F);
        #pragma unroll
        for (int it = 0; it < 4; it++) {
            const int idx  = tid + it * 512;      // 2048 float4
            const int node = idx >> 5;
            const int c4   = idx & 31;            // covers k-pairs 2c4, 2c4+1
            float4 v = X4[idx];
            uint2 o;
            o.x = pack_h2(v.x, v.y);
            o.y = pack_h2(v.z, v.w);
            *(uint2*)&Xp[node * XS2 + c4 * 2] = o;
        }
    }
    __syncthreads();

    float acc[4][4];
    #pragma unroll
    for (int j = 0; j < 4; j++)
        #pragma unroll
        for (int r = 0; r < 4; r++)
            acc[j][r] = 0.0f;

    const u32* pA = Xp + (m0 + gid) * XS2 + tig;     // a0; a2=+4; a1=+8*XS2; a3=+8*XS2+4
    const u32* pB = Wp + tig * WS2 + n0 + gid;       // b0[j]=+8j; b1[j]=+4*WS2+8j

    // ---- 8 k16-steps, 2-deep fragment pipeline ----
    u32 a[2][4], b0[2][4], b1[2][4];
    {
        a[0][0] = pA[0];
        a[0][1] = pA[8 * XS2];
        a[0][2] = pA[4];
        a[0][3] = pA[8 * XS2 + 4];
        #pragma unroll
        for (int j = 0; j < 4; j++) {
            b0[0][j] = pB[8 * j];
            b1[0][j] = pB[4 * WS2 + 8 * j];
        }
    }

    #pragma unroll
    for (int s = 0; s < 8; s++) {
        const int cur = s & 1, nxt = cur ^ 1;
        if (s < 7) {
            const u32* qa = pA + (s + 1) * 8;
            const u32* qb = pB + (s + 1) * 8 * WS2;
            a[nxt][0] = qa[0];
            a[nxt][1] = qa[8 * XS2];
            a[nxt][2] = qa[4];
            a[nxt][3] = qa[8 * XS2 + 4];
            #pragma unroll
            for (int j = 0; j < 4; j++) {
                b0[nxt][j] = qb[8 * j];
                b1[nxt][j] = qb[4 * WS2 + 8 * j];
            }
        }
        #pragma unroll
        for (int j = 0; j < 4; j++)
            mma_f16(acc[j], a[cur][0], a[cur][1], a[cur][2], a[cur][3],
                    b0[cur][j], b1[cur][j]);
    }

    // ---- epilogue: bias + coalesced float2 stores ----
    float bb[4][2];
    #pragma unroll
    for (int j = 0; j < 4; j++) {
        const int col = n0 + 8 * j + 2 * tig;
        bb[j][0] = __ldg(bias + (size_t)h * OUT_F + col);
        bb[j][1] = __ldg(bias + (size_t)h * OUT_F + col + 1);
    }

    const int node0 = g * NPG + m0 + gid;
    #pragma unroll
    for (int j = 0; j < 4; j++) {
        const int col = n0 + 8 * j + 2 * tig;
        float2 v0 = make_float2(acc[j][0] + bb[j][0], acc[j][1] + bb[j][1]);
        float2 v1 = make_float2(acc[j][2] + bb[j][0], acc[j][3] + bb[j][1]);
        *(float2*)&out[(size_t)node0 * OUT_F + col]       = v0;
        *(float2*)&out[(size_t)(node0 + 8) * OUT_F + col] = v1;
    }
}

extern "C" void kernel_launch(void* const* d_in, const int* in_sizes, int n_in,
                              void* d_out, int out_size)
{
    const float* inputs = (const float*)d_in[0];
    const int*   head   = (const int*)d_in[2];
    const float* kern   = (const float*)d_in[3];
    const float* bias   = (const float*)d_in[4];
    float*       out    = (float*)d_out;
    const int n_graphs  = in_sizes[2];   // 256

    static bool attr_set = false;
    if (!attr_set) {
        cudaFuncSetAttribute(mhl_mma_kernel, cudaFuncAttributeMaxDynamicSharedMemorySize, SMEM_BYTES);
        attr_set = true;
    }
    mhl_mma_kernel<<<n_graphs, 512, SMEM_BYTES>>>(inputs, head, kern, bias, out);
}